// round 2
// baseline (speedup 1.0000x reference)
#include <cuda_runtime.h>
#include <cuda_bf16.h>
#include <cstdint>

#define BS   8192   // tokens (4*2048)
#define HID  1024
#define CB   8192   // codebook size
#define LOSS_WEIGHT 0.1f

// GEMM tiling
#define BM 128
#define BN 128
#define BK 32
#define NKT (HID / BK)          // 32 k-tiles
#define STRIDE 40               // smem row stride in bf16 (32 + 8 pad), 80 B
#define STAGE_ELEMS (128 * STRIDE)  // per operand per stage

// ============================ scratch ============================
__device__ float g_logits[(size_t)BS * CB];          // 256 MB
__device__ float g_cross [(size_t)BS * CB];          // 256 MB
__device__ __nv_bfloat16 g_A1[(size_t)BS * HID];     // hidden_states bf16
__device__ __nv_bfloat16 g_A2[(size_t)BS * HID];     // target bf16
__device__ __nv_bfloat16 g_B1[(size_t)CB * HID];     // W^T bf16 [C,H]
__device__ __nv_bfloat16 g_B2[(size_t)CB * HID];     // codebook bf16
__device__ float g_csq[CB];
__device__ float g_tsq[BS];
__device__ float g_ptl[BS];
__device__ int   g_i64;   // 1 if token_type_ids buffer is int64-layout

// ============================ PTX helpers ============================
__device__ __forceinline__ uint32_t smem_u32(const void* p) {
    uint32_t a;
    asm("{ .reg .u64 t; cvta.to.shared.u64 t, %1; cvt.u32.u64 %0, t; }" : "=r"(a) : "l"(p));
    return a;
}
__device__ __forceinline__ void cp16(uint32_t dst, const void* src) {
    asm volatile("cp.async.cg.shared.global [%0], [%1], 16;" :: "r"(dst), "l"(src));
}
__device__ __forceinline__ void cp_commit() {
    asm volatile("cp.async.commit_group;" ::: "memory");
}
template <int N>
__device__ __forceinline__ void cp_wait() {
    asm volatile("cp.async.wait_group %0;" :: "n"(N) : "memory");
}
__device__ __forceinline__ void ldm_x4(uint32_t& r0, uint32_t& r1, uint32_t& r2,
                                       uint32_t& r3, uint32_t addr) {
    asm volatile("ldmatrix.sync.aligned.m8n8.x4.shared.b16 {%0,%1,%2,%3}, [%4];"
                 : "=r"(r0), "=r"(r1), "=r"(r2), "=r"(r3) : "r"(addr));
}
__device__ __forceinline__ void mma_bf16(float* d, const uint32_t* a, const uint32_t* b) {
    asm volatile(
        "mma.sync.aligned.m16n8k16.row.col.f32.bf16.bf16.f32 "
        "{%0,%1,%2,%3}, {%4,%5,%6,%7}, {%8,%9}, {%0,%1,%2,%3};"
        : "+f"(d[0]), "+f"(d[1]), "+f"(d[2]), "+f"(d[3])
        : "r"(a[0]), "r"(a[1]), "r"(a[2]), "r"(a[3]), "r"(b[0]), "r"(b[1]));
}

// ============================ prep kernels ============================
__global__ void k_conv(const float* __restrict__ in, int which, int n4) {
    int i = blockIdx.x * blockDim.x + threadIdx.x;
    if (i >= n4) return;
    __nv_bfloat16* out = (which == 0) ? g_A1 : (which == 1) ? g_A2 : g_B2;
    float4 v = ((const float4*)in)[i];
    __nv_bfloat162 lo = __floats2bfloat162_rn(v.x, v.y);
    __nv_bfloat162 hi = __floats2bfloat162_rn(v.z, v.w);
    ((__nv_bfloat162*)out)[2 * i]     = lo;
    ((__nv_bfloat162*)out)[2 * i + 1] = hi;
}

// W [HID, CB] f32 -> g_B1 [CB, HID] bf16
__global__ void k_transpose(const float* __restrict__ W) {
    __shared__ float tile[32][33];
    int c0 = blockIdx.x * 32, h0 = blockIdx.y * 32;
    int tx = threadIdx.x, ty = threadIdx.y;
    for (int j = ty; j < 32; j += 8)
        tile[j][tx] = W[(size_t)(h0 + j) * CB + c0 + tx];
    __syncthreads();
    for (int j = ty; j < 32; j += 8)
        g_B1[(size_t)(c0 + j) * HID + h0 + tx] = __float2bfloat16(tile[tx][j]);
}

__global__ void k_rowsq(const float* __restrict__ in, int which) {
    float* out = which ? g_tsq : g_csq;
    int warp = (blockIdx.x * 256 + threadIdx.x) >> 5;
    int lane = threadIdx.x & 31;
    const float4* p = (const float4*)(in + (size_t)warp * HID);
    float s = 0.f;
    #pragma unroll
    for (int i = lane; i < HID / 4; i += 32) {
        float4 v = p[i];
        s += v.x * v.x + v.y * v.y + v.z * v.z + v.w * v.w;
    }
    #pragma unroll
    for (int o = 16; o; o >>= 1) s += __shfl_xor_sync(0xffffffffu, s, o);
    if (!lane) out[warp] = s;
}

// detect int64 vs int32 layout of token_type_ids (values are 0/1)
__global__ void k_detect(const int* __restrict__ tti32) {
    __shared__ int s[256];
    int acc = 0;
    for (int i = threadIdx.x; i < BS / 2; i += 256) acc += (tti32[2 * i + 1] != 0);
    s[threadIdx.x] = acc;
    __syncthreads();
    for (int o = 128; o; o >>= 1) {
        if (threadIdx.x < o) s[threadIdx.x] += s[threadIdx.x + o];
        __syncthreads();
    }
    if (threadIdx.x == 0) g_i64 = (s[0] == 0) ? 1 : 0;
}

// ============================ GEMM (mma.sync bf16) ============================
// C[m0:m0+128, n0:n0+128] = A[m, :] . B[n, :]^T  (both K-major [rows, HID])
__global__ void __launch_bounds__(256) k_gemm(int which) {
    const __nv_bfloat16* __restrict__ A = (which == 0) ? g_A1 : g_A2;
    const __nv_bfloat16* __restrict__ B = (which == 0) ? g_B1 : g_B2;
    float* __restrict__ C = (which == 0) ? g_logits : g_cross;

    __shared__ __align__(128) __nv_bfloat16 smem[4 * STAGE_ELEMS];  // 40960 B

    const int tid = threadIdx.x;
    const int wid = tid >> 5, lane = tid & 31;
    const int warp_m = wid & 3;      // 4 warps along M, 32 rows each
    const int warp_n = wid >> 2;     // 2 warps along N, 64 cols each
    const int m0 = blockIdx.y * BM, n0 = blockIdx.x * BN;

    const uint32_t s_base = smem_u32(smem);
    // stage st: A at st*2*STAGE_ELEMS, B at that + STAGE_ELEMS (bf16 units)

    // cp.async source/dest precompute: 512 16B-chunks per operand per stage
    // chunk c: row = c>>2, q = c&3 -> gmem row*HID + kt*32 + q*8 ; smem row*STRIDE + q*8
    const int c0i = tid, c1i = tid + 256;
    const int r0 = c0i >> 2, q0 = c0i & 3;
    const int r1 = c1i >> 2, q1 = c1i & 3;
    const __nv_bfloat16* gA0 = A + (size_t)(m0 + r0) * HID + q0 * 8;
    const __nv_bfloat16* gA1 = A + (size_t)(m0 + r1) * HID + q1 * 8;
    const __nv_bfloat16* gB0 = B + (size_t)(n0 + r0) * HID + q0 * 8;
    const __nv_bfloat16* gB1 = B + (size_t)(n0 + r1) * HID + q1 * 8;
    const uint32_t sA0 = (uint32_t)(r0 * STRIDE + q0 * 8) * 2;
    const uint32_t sA1 = (uint32_t)(r1 * STRIDE + q1 * 8) * 2;

    auto prefetch = [&](int kt, int st) {
        uint32_t base = s_base + (uint32_t)(st * 2 * STAGE_ELEMS) * 2;
        uint32_t baseB = base + (uint32_t)STAGE_ELEMS * 2;
        int ko = kt * BK;
        cp16(base + sA0, gA0 + ko);
        cp16(base + sA1, gA1 + ko);
        cp16(baseB + sA0, gB0 + ko);
        cp16(baseB + sA1, gB1 + ko);
        cp_commit();
    };

    // per-lane ldmatrix base offsets (bytes)
    // A tile (mt,ks): row = warp_m*32 + mt*16 + (lane&15), col8 = ((lane>>4)&1)*8
    const uint32_t a_off = (uint32_t)((warp_m * 32 + (lane & 15)) * STRIDE
                                      + ((lane >> 4) & 1) * 8) * 2;
    // B pair-tile (pt,ks): row = warp_n*64 + pt*16 + ((lane&16)?8:0) + (lane&7),
    //                      col8 = ((lane&8)?8:0)
    const uint32_t b_off = (uint32_t)((warp_n * 64 + ((lane & 16) >> 1) + (lane & 7)) * STRIDE
                                      + ((lane & 8))) * 2;

    float acc[2][8][4];
    #pragma unroll
    for (int i = 0; i < 2; ++i)
        #pragma unroll
        for (int j = 0; j < 8; ++j)
            #pragma unroll
            for (int k = 0; k < 4; ++k) acc[i][j][k] = 0.f;

    prefetch(0, 0);

    for (int kt = 0; kt < NKT; ++kt) {
        const int st = kt & 1;
        if (kt + 1 < NKT) { prefetch(kt + 1, st ^ 1); cp_wait<1>(); }
        else              { cp_wait<0>(); }
        __syncthreads();

        const uint32_t aS = s_base + (uint32_t)(st * 2 * STAGE_ELEMS) * 2 + a_off;
        const uint32_t bS = s_base + (uint32_t)(st * 2 * STAGE_ELEMS + STAGE_ELEMS) * 2 + b_off;

        #pragma unroll
        for (int ks = 0; ks < 2; ++ks) {
            uint32_t a[2][4], b[8][2];
            #pragma unroll
            for (int mt = 0; mt < 2; ++mt)
                ldm_x4(a[mt][0], a[mt][1], a[mt][2], a[mt][3],
                       aS + (uint32_t)(mt * 16 * STRIDE + ks * 16) * 2);
            #pragma unroll
            for (int pt = 0; pt < 4; ++pt) {
                uint32_t r0_, r1_, r2_, r3_;
                ldm_x4(r0_, r1_, r2_, r3_,
                       bS + (uint32_t)(pt * 16 * STRIDE + ks * 16) * 2);
                b[pt * 2][0] = r0_;     b[pt * 2][1] = r1_;
                b[pt * 2 + 1][0] = r2_; b[pt * 2 + 1][1] = r3_;
            }
            #pragma unroll
            for (int mt = 0; mt < 2; ++mt)
                #pragma unroll
                for (int nt = 0; nt < 8; ++nt)
                    mma_bf16(acc[mt][nt], a[mt], b[nt]);
        }
        __syncthreads();
    }

    // epilogue: c-frag: {c0,c1}: row = l/4, col = (l%4)*2 ; {c2,c3}: row+8
    const int er = m0 + warp_m * 32 + (lane >> 2);
    const int ec = n0 + warp_n * 64 + (lane & 3) * 2;
    #pragma unroll
    for (int mt = 0; mt < 2; ++mt) {
        #pragma unroll
        for (int nt = 0; nt < 8; ++nt) {
            float* p0 = C + (size_t)(er + mt * 16)     * CB + ec + nt * 8;
            float* p1 = C + (size_t)(er + mt * 16 + 8) * CB + ec + nt * 8;
            *(float2*)p0 = make_float2(acc[mt][nt][0], acc[mt][nt][1]);
            *(float2*)p1 = make_float2(acc[mt][nt][2], acc[mt][nt][3]);
        }
    }
}

// ============================ softmax-weighted MSE reduction ============================
__global__ void __launch_bounds__(256) k_reduce(const float* __restrict__ bias,
                                                const int* __restrict__ tti32) {
    const int tok = blockIdx.x;
    const float4* lrow = (const float4*)(g_logits + (size_t)tok * CB);
    const float4* xrow = (const float4*)(g_cross  + (size_t)tok * CB);
    const float4* b4   = (const float4*)bias;
    const float4* c4   = (const float4*)g_csq;

    float m = -1e30f, z = 0.f, acc = 0.f;
    for (int i = threadIdx.x; i < CB / 4; i += 256) {
        float4 l4 = lrow[i], x4 = xrow[i], bb = b4[i], cc = c4[i];
        float ls[4] = {l4.x + bb.x, l4.y + bb.y, l4.z + bb.z, l4.w + bb.w};
        float xs[4] = {cc.x - 2.f * x4.x, cc.y - 2.f * x4.y,
                       cc.z - 2.f * x4.z, cc.w - 2.f * x4.w};
        #pragma unroll
        for (int j = 0; j < 4; ++j) {
            float l = ls[j];
            if (l > m) { float s = __expf(m - l); z *= s; acc *= s; m = l; }
            float e = __expf(l - m);
            z += e; acc += e * xs[j];
        }
    }
    __shared__ float sm[256], sz[256], sn[256];
    sm[threadIdx.x] = m; sz[threadIdx.x] = z; sn[threadIdx.x] = acc;
    __syncthreads();
    for (int o = 128; o; o >>= 1) {
        if (threadIdx.x < o) {
            float m2 = sm[threadIdx.x + o], z2 = sz[threadIdx.x + o], n2 = sn[threadIdx.x + o];
            float M = fmaxf(sm[threadIdx.x], m2);
            float s1 = __expf(sm[threadIdx.x] - M), s2 = __expf(m2 - M);
            sm[threadIdx.x] = M;
            sz[threadIdx.x] = sz[threadIdx.x] * s1 + z2 * s2;
            sn[threadIdx.x] = sn[threadIdx.x] * s1 + n2 * s2;
        }
        __syncthreads();
    }
    if (threadIdx.x == 0) {
        int tv = g_i64 ? tti32[2 * tok] : tti32[tok];
        float loss = (g_tsq[tok] + sn[0] / sz[0]) * (1.0f / (float)HID);
        g_ptl[tok] = (tv == 1) ? loss : 0.f;
    }
}

__global__ void k_final(float* __restrict__ out) {
    __shared__ float s[256];
    float acc = 0.f;
    for (int i = threadIdx.x; i < BS; i += 256) acc += g_ptl[i];
    s[threadIdx.x] = acc;
    __syncthreads();
    for (int o = 128; o; o >>= 1) {
        if (threadIdx.x < o) s[threadIdx.x] += s[threadIdx.x + o];
        __syncthreads();
    }
    if (threadIdx.x == 0) out[0] = s[0] * LOSS_WEIGHT;
}

// ============================ launch ============================
extern "C" void kernel_launch(void* const* d_in, const int* in_sizes, int n_in,
                              void* d_out, int out_size) {
    const float* hs   = (const float*)d_in[0];
    const int*   tti  = (const int*)  d_in[1];   // int32 or int64 view; auto-detected
    const float* tgt  = (const float*)d_in[2];
    const float* cbk  = (const float*)d_in[3];
    const float* W    = (const float*)d_in[4];
    const float* bias = (const float*)d_in[5];
    float* out = (float*)d_out;

    const int n4 = BS * HID / 4;
    k_conv<<<n4 / 256, 256>>>(hs,  0, n4);
    k_conv<<<n4 / 256, 256>>>(tgt, 1, n4);
    k_conv<<<n4 / 256, 256>>>(cbk, 2, n4);
    k_transpose<<<dim3(CB / 32, HID / 32), dim3(32, 8)>>>(W);
    k_rowsq<<<CB / 8, 256>>>(cbk, 0);
    k_rowsq<<<BS / 8, 256>>>(tgt, 1);
    k_detect<<<1, 256>>>(tti);

    dim3 gg(CB / BN, BS / BM);
    k_gemm<<<gg, 256>>>(0);   // logits = HS . W
    k_gemm<<<gg, 256>>>(1);   // cross  = T . codebook^T

    k_reduce<<<BS, 256>>>(bias, tti);
    k_final<<<1, 256>>>(out);
}